// round 2
// baseline (speedup 1.0000x reference)
#include <cuda_runtime.h>
#include <cstddef>

// Problem dims (fixed by dataset)
#define NTC 400000
#define NMC 40000
#define CH  64
#define FT  384

// ---------------- scratch (static __device__ — no allocations) ----------------
__device__ float g_xt0[(size_t)NTC * CH];
__device__ float g_xt1[(size_t)NTC * CH];
__device__ float g_xt2[(size_t)NTC * CH];
__device__ float g_aggt[(size_t)NTC * CH];
__device__ float g_xm0[(size_t)NMC * CH];
__device__ float g_xm1[(size_t)NMC * CH];
__device__ float g_xm2[(size_t)NMC * CH];
__device__ float g_aggm[(size_t)NMC * CH];
__device__ int   g_cnt_t[NTC];
__device__ int   g_cnt_m[NMC];
__device__ float g_inv_t[NTC];
__device__ float g_inv_m[NMC];

// ---------------- packed f32x2 FMA (FFMA2 — only reachable via PTX) ------------
union F2U { float2 f; unsigned long long u; };
__device__ __forceinline__ float2 ffma2(float2 a, float2 b, float2 c) {
    F2U A, B, Cc, D;
    A.f = a; B.f = b; Cc.f = c;
    asm("fma.rn.f32x2 %0, %1, %2, %3;" : "=l"(D.u) : "l"(A.u), "l"(B.u), "l"(Cc.u));
    return D.f;
}

// ---------------- degree / recip ----------------
__global__ void degree_kernel(const int* __restrict__ esrc, const int* __restrict__ edst, int E) {
    int t = blockIdx.x * blockDim.x + threadIdx.x;
    if (t < E) {
        atomicAdd(&g_cnt_t[esrc[t]], 1);
        atomicAdd(&g_cnt_m[edst[t]], 1);
    }
}

__global__ void recip_kernel(const int* __restrict__ cnt, float* __restrict__ inv, int n) {
    int t = blockIdx.x * blockDim.x + threadIdx.x;
    if (t < n) inv[t] = 1.0f / fmaxf((float)cnt[t], 1.0f);
}

// ---------------- mentor encoder: x_m0 = emb_m[mentor_id] ----------------
__global__ void gather_rows_kernel(const float* __restrict__ src, const int* __restrict__ ids,
                                   float* __restrict__ out, int n) {
    int t = blockIdx.x * blockDim.x + threadIdx.x;
    int e = t >> 4;
    if (e >= n) return;
    int c4 = (t & 15) << 2;
    int id = __ldg(&ids[e]);
    float4 v = *reinterpret_cast<const float4*>(&src[(size_t)id * CH + c4]);
    *reinterpret_cast<float4*>(&out[(size_t)e * CH + c4]) = v;
}

// ---------------- edge scatter-add: agg[sidx[e]] += feat[gidx[e]] --------------
__global__ void scatter_kernel(const float* __restrict__ feat, const int* __restrict__ gidx,
                               const int* __restrict__ sidx, float* __restrict__ agg, int E) {
    int t = blockIdx.x * blockDim.x + threadIdx.x;
    int e = t >> 4;
    if (e >= E) return;
    int c4 = (t & 15) << 2;
    int s = __ldg(&gidx[e]);
    int d = __ldg(&sidx[e]);
    float4 v = *reinterpret_cast<const float4*>(&feat[(size_t)s * CH + c4]);
    float* p = &agg[(size_t)d * CH + c4];
    asm volatile("red.global.add.v4.f32 [%0], {%1, %2, %3, %4};"
                 :: "l"(p), "f"(v.x), "f"(v.y), "f"(v.z), "f"(v.w) : "memory");
}

// ---------------- encoder GEMM: out = X[M,384] @ W[64,384]^T + b + emb[id] ----
// BM=128, BN=64, BK=32, 256 threads, 8x4 micro-tile per thread via f32x2 pairs.
__global__ __launch_bounds__(256)
void encoder_kernel(const float* __restrict__ X, const float* __restrict__ W,
                    const float* __restrict__ bias, const float* __restrict__ emb,
                    const int* __restrict__ ids, float* __restrict__ out, int M) {
    __shared__ float As[32][132];
    __shared__ float Ws[32][68];
    int tid = threadIdx.x;
    int tx = tid & 15, ty = tid >> 4;
    int row0 = blockIdx.x * 128;

    float2 acc[4][4];
#pragma unroll
    for (int i = 0; i < 4; i++)
#pragma unroll
        for (int j = 0; j < 4; j++) acc[i][j] = make_float2(0.f, 0.f);

    for (int kt = 0; kt < FT; kt += 32) {
#pragma unroll
        for (int i = 0; i < 4; i++) {
            int idx = tid + 256 * i;
            int r = idx >> 3;
            int kq = (idx & 7) << 2;
            int grow = row0 + r;
            float4 v = make_float4(0.f, 0.f, 0.f, 0.f);
            if (grow < M)
                v = *reinterpret_cast<const float4*>(&X[(size_t)grow * FT + kt + kq]);
            As[kq + 0][r] = v.x; As[kq + 1][r] = v.y;
            As[kq + 2][r] = v.z; As[kq + 3][r] = v.w;
        }
#pragma unroll
        for (int i = 0; i < 2; i++) {
            int idx = tid + 256 * i;
            int c = idx >> 3;
            int kq = (idx & 7) << 2;
            float4 v = *reinterpret_cast<const float4*>(&W[(size_t)c * FT + kt + kq]);
            Ws[kq + 0][c] = v.x; Ws[kq + 1][c] = v.y;
            Ws[kq + 2][c] = v.z; Ws[kq + 3][c] = v.w;
        }
        __syncthreads();
#pragma unroll
        for (int k = 0; k < 32; k++) {
            float4 a0 = *reinterpret_cast<const float4*>(&As[k][ty * 8]);
            float4 a1 = *reinterpret_cast<const float4*>(&As[k][ty * 8 + 4]);
            float4 w  = *reinterpret_cast<const float4*>(&Ws[k][tx * 4]);
            float2 ap[4] = { {a0.x, a0.y}, {a0.z, a0.w}, {a1.x, a1.y}, {a1.z, a1.w} };
            float2 wd[4] = { {w.x, w.x}, {w.y, w.y}, {w.z, w.z}, {w.w, w.w} };
#pragma unroll
            for (int rp = 0; rp < 4; rp++)
#pragma unroll
                for (int j = 0; j < 4; j++)
                    acc[rp][j] = ffma2(ap[rp], wd[j], acc[rp][j]);
        }
        __syncthreads();
    }

    float4 bv = *reinterpret_cast<const float4*>(&bias[tx * 4]);
#pragma unroll
    for (int rp = 0; rp < 4; rp++) {
#pragma unroll
        for (int s = 0; s < 2; s++) {
            int r = row0 + ty * 8 + rp * 2 + s;
            if (r < M) {
                int nid = __ldg(&ids[r]);
                float4 ev = *reinterpret_cast<const float4*>(&emb[(size_t)nid * CH + tx * 4]);
                float4 o;
                o.x = (s ? acc[rp][0].y : acc[rp][0].x) + bv.x + ev.x;
                o.y = (s ? acc[rp][1].y : acc[rp][1].x) + bv.y + ev.y;
                o.z = (s ? acc[rp][2].y : acc[rp][2].x) + bv.z + ev.z;
                o.w = (s ? acc[rp][3].y : acc[rp][3].x) + bv.w + ev.w;
                *reinterpret_cast<float4*>(&out[(size_t)r * CH + tx * 4]) = o;
            }
        }
    }
}

// ---------------- fused SAGE layer GEMM --------------------------------------
// out[i][c] = act( (agg[i]/cnt[i]) @ Wl^T + x[i] @ Wr^T + b )
// Treated as one K=128 GEMM: 4 BK=32 subtiles (2 from agg*inv/Wl, 2 from x/Wr).
template <bool RELU>
__global__ __launch_bounds__(256)
void sage_kernel(const float* __restrict__ Agg, const float* __restrict__ inv,
                 const float* __restrict__ Xs,
                 const float* __restrict__ Wl, const float* __restrict__ Wr,
                 const float* __restrict__ bias, float* __restrict__ out, int M) {
    __shared__ float As[32][132];
    __shared__ float Ws[32][68];
    int tid = threadIdx.x;
    int tx = tid & 15, ty = tid >> 4;
    int row0 = blockIdx.x * 128;

    float2 acc[4][4];
#pragma unroll
    for (int i = 0; i < 4; i++)
#pragma unroll
        for (int j = 0; j < 4; j++) acc[i][j] = make_float2(0.f, 0.f);

    for (int tt = 0; tt < 4; tt++) {
        const float* A  = (tt < 2) ? Agg : Xs;
        const float* Wp = (tt < 2) ? Wl  : Wr;
        bool do_scale = (tt < 2);
        int kt = (tt & 1) * 32;
#pragma unroll
        for (int i = 0; i < 4; i++) {
            int idx = tid + 256 * i;
            int r = idx >> 3;
            int kq = (idx & 7) << 2;
            int grow = row0 + r;
            float4 v = make_float4(0.f, 0.f, 0.f, 0.f);
            if (grow < M) {
                v = *reinterpret_cast<const float4*>(&A[(size_t)grow * CH + kt + kq]);
                if (do_scale) {
                    float sc = __ldg(&inv[grow]);
                    v.x *= sc; v.y *= sc; v.z *= sc; v.w *= sc;
                }
            }
            As[kq + 0][r] = v.x; As[kq + 1][r] = v.y;
            As[kq + 2][r] = v.z; As[kq + 3][r] = v.w;
        }
#pragma unroll
        for (int i = 0; i < 2; i++) {
            int idx = tid + 256 * i;
            int c = idx >> 3;
            int kq = (idx & 7) << 2;
            float4 v = *reinterpret_cast<const float4*>(&Wp[(size_t)c * CH + kt + kq]);
            Ws[kq + 0][c] = v.x; Ws[kq + 1][c] = v.y;
            Ws[kq + 2][c] = v.z; Ws[kq + 3][c] = v.w;
        }
        __syncthreads();
#pragma unroll
        for (int k = 0; k < 32; k++) {
            float4 a0 = *reinterpret_cast<const float4*>(&As[k][ty * 8]);
            float4 a1 = *reinterpret_cast<const float4*>(&As[k][ty * 8 + 4]);
            float4 w  = *reinterpret_cast<const float4*>(&Ws[k][tx * 4]);
            float2 ap[4] = { {a0.x, a0.y}, {a0.z, a0.w}, {a1.x, a1.y}, {a1.z, a1.w} };
            float2 wd[4] = { {w.x, w.x}, {w.y, w.y}, {w.z, w.z}, {w.w, w.w} };
#pragma unroll
            for (int rp = 0; rp < 4; rp++)
#pragma unroll
                for (int j = 0; j < 4; j++)
                    acc[rp][j] = ffma2(ap[rp], wd[j], acc[rp][j]);
        }
        __syncthreads();
    }

    float4 bv = *reinterpret_cast<const float4*>(&bias[tx * 4]);
#pragma unroll
    for (int rp = 0; rp < 4; rp++) {
#pragma unroll
        for (int s = 0; s < 2; s++) {
            int r = row0 + ty * 8 + rp * 2 + s;
            if (r < M) {
                float4 o;
                o.x = (s ? acc[rp][0].y : acc[rp][0].x) + bv.x;
                o.y = (s ? acc[rp][1].y : acc[rp][1].x) + bv.y;
                o.z = (s ? acc[rp][2].y : acc[rp][2].x) + bv.z;
                o.w = (s ? acc[rp][3].y : acc[rp][3].x) + bv.w;
                if (RELU) {
                    o.x = fmaxf(o.x, 0.f); o.y = fmaxf(o.y, 0.f);
                    o.z = fmaxf(o.z, 0.f); o.w = fmaxf(o.w, 0.f);
                }
                *reinterpret_cast<float4*>(&out[(size_t)r * CH + tx * 4]) = o;
            }
        }
    }
}

// ---------------- edge dot-product classifier --------------------------------
__global__ void edge_dot_kernel(const float* __restrict__ xt, const float* __restrict__ xm,
                                const int* __restrict__ es, const int* __restrict__ ed,
                                float* __restrict__ out, int E) {
    int t = blockIdx.x * blockDim.x + threadIdx.x;
    int e = t >> 4;
    if (e >= E) return;
    int c4 = (t & 15) << 2;
    int s = __ldg(&es[e]);
    int d = __ldg(&ed[e]);
    float4 a = *reinterpret_cast<const float4*>(&xt[(size_t)s * CH + c4]);
    float4 b = *reinterpret_cast<const float4*>(&xm[(size_t)d * CH + c4]);
    float p = a.x * b.x + a.y * b.y + a.z * b.z + a.w * b.w;
    p += __shfl_down_sync(0xffffffffu, p, 8);
    p += __shfl_down_sync(0xffffffffu, p, 4);
    p += __shfl_down_sync(0xffffffffu, p, 2);
    p += __shfl_down_sync(0xffffffffu, p, 1);
    if ((t & 15) == 0) out[e] = p;
}

// ---------------- launch -----------------------------------------------------
extern "C" void kernel_launch(void* const* d_in, const int* in_sizes, int n_in,
                              void* d_out, int out_size) {
    const float* x_thesis  = (const float*)d_in[0];
    const int*   thesis_id = (const int*)d_in[1];
    const int*   mentor_id = (const int*)d_in[2];
    const int*   edge_src  = (const int*)d_in[3];
    const int*   edge_dst  = (const int*)d_in[4];
    const int*   el_src    = (const int*)d_in[5];
    const int*   el_dst    = (const int*)d_in[6];
    const float* lin_W     = (const float*)d_in[7];
    const float* lin_b     = (const float*)d_in[8];
    const float* emb_t     = (const float*)d_in[9];
    const float* emb_m     = (const float*)d_in[10];
    const float* Wl_tm0    = (const float*)d_in[11];
    const float* Wr_tm0    = (const float*)d_in[12];
    const float* b_tm0     = (const float*)d_in[13];
    const float* Wl_mt0    = (const float*)d_in[14];
    const float* Wr_mt0    = (const float*)d_in[15];
    const float* b_mt0     = (const float*)d_in[16];
    const float* Wl_tm1    = (const float*)d_in[17];
    const float* Wr_tm1    = (const float*)d_in[18];
    const float* b_tm1     = (const float*)d_in[19];
    const float* Wl_mt1    = (const float*)d_in[20];
    const float* Wr_mt1    = (const float*)d_in[21];
    const float* b_mt1     = (const float*)d_in[22];
    float* out = (float*)d_out;

    int nt = in_sizes[1];
    int nm = in_sizes[2];
    int E  = in_sizes[3];
    int EL = in_sizes[5];

    void *p_xt0, *p_xt1, *p_xt2, *p_aggt, *p_xm0, *p_xm1, *p_xm2, *p_aggm;
    void *p_cntt, *p_cntm, *p_invt, *p_invm;
    cudaGetSymbolAddress(&p_xt0, g_xt0);   cudaGetSymbolAddress(&p_xt1, g_xt1);
    cudaGetSymbolAddress(&p_xt2, g_xt2);   cudaGetSymbolAddress(&p_aggt, g_aggt);
    cudaGetSymbolAddress(&p_xm0, g_xm0);   cudaGetSymbolAddress(&p_xm1, g_xm1);
    cudaGetSymbolAddress(&p_xm2, g_xm2);   cudaGetSymbolAddress(&p_aggm, g_aggm);
    cudaGetSymbolAddress(&p_cntt, g_cnt_t); cudaGetSymbolAddress(&p_cntm, g_cnt_m);
    cudaGetSymbolAddress(&p_invt, g_inv_t); cudaGetSymbolAddress(&p_invm, g_inv_m);

    float* xt0 = (float*)p_xt0; float* xt1 = (float*)p_xt1; float* xt2 = (float*)p_xt2;
    float* aggt = (float*)p_aggt;
    float* xm0 = (float*)p_xm0; float* xm1 = (float*)p_xm1; float* xm2 = (float*)p_xm2;
    float* aggm = (float*)p_aggm;
    int* cntt = (int*)p_cntt; int* cntm = (int*)p_cntm;
    float* invt = (float*)p_invt; float* invm = (float*)p_invm;

    const int TB = 256;
    int gridE16  = (E * 16 + TB - 1) / TB;
    int gridEL16 = (EL * 16 + TB - 1) / TB;
    int gridNT   = (nt + 127) / 128;
    int gridNM   = (nm + 127) / 128;

    // degree + recip
    cudaMemsetAsync(cntt, 0, (size_t)nt * sizeof(int));
    cudaMemsetAsync(cntm, 0, (size_t)nm * sizeof(int));
    degree_kernel<<<(E + TB - 1) / TB, TB>>>(edge_src, edge_dst, E);
    recip_kernel<<<(nt + TB - 1) / TB, TB>>>(cntt, invt, nt);
    recip_kernel<<<(nm + TB - 1) / TB, TB>>>(cntm, invm, nm);

    // node encoders
    gather_rows_kernel<<<(nm * 16 + TB - 1) / TB, TB>>>(emb_m, mentor_id, xm0, nm);
    encoder_kernel<<<gridNT, TB>>>(x_thesis, lin_W, lin_b, emb_t, thesis_id, xt0, nt);

    // ---- layer 0 ----
    cudaMemsetAsync(aggm, 0, (size_t)nm * CH * sizeof(float));
    scatter_kernel<<<gridE16, TB>>>(xt0, edge_src, edge_dst, aggm, E);
    cudaMemsetAsync(aggt, 0, (size_t)nt * CH * sizeof(float));
    scatter_kernel<<<gridE16, TB>>>(xm0, edge_dst, edge_src, aggt, E);
    sage_kernel<true><<<gridNM, TB>>>(aggm, invm, xm0, Wl_tm0, Wr_tm0, b_tm0, xm1, nm);
    sage_kernel<true><<<gridNT, TB>>>(aggt, invt, xt0, Wl_mt0, Wr_mt0, b_mt0, xt1, nt);

    // ---- layer 1 ----
    cudaMemsetAsync(aggm, 0, (size_t)nm * CH * sizeof(float));
    scatter_kernel<<<gridE16, TB>>>(xt1, edge_src, edge_dst, aggm, E);
    cudaMemsetAsync(aggt, 0, (size_t)nt * CH * sizeof(float));
    scatter_kernel<<<gridE16, TB>>>(xm1, edge_dst, edge_src, aggt, E);
    sage_kernel<false><<<gridNM, TB>>>(aggm, invm, xm1, Wl_tm1, Wr_tm1, b_tm1, xm2, nm);
    sage_kernel<false><<<gridNT, TB>>>(aggt, invt, xt1, Wl_mt1, Wr_mt1, b_mt1, xt2, nt);

    // classifier
    edge_dot_kernel<<<gridEL16, TB>>>(xt2, xm2, el_src, el_dst, out, EL);
}

// round 4
// speedup vs baseline: 1.1135x; 1.1135x over previous
#include <cuda_runtime.h>
#include <cstddef>

// Problem dims (fixed by dataset)
#define NTC 400000
#define NMC 40000
#define CH  64
#define FT  384

// ---------------- scratch (static __device__ — no allocations) ----------------
__device__ float g_xt0[(size_t)NTC * CH];
__device__ float g_xt1[(size_t)NTC * CH];
__device__ float g_xt2[(size_t)NTC * CH];
__device__ float g_aggt[(size_t)NTC * CH];   // scattered pre-transformed mentor rows
__device__ float g_xm0[(size_t)NMC * CH];
__device__ float g_xm1[(size_t)NMC * CH];
__device__ float g_xm2[(size_t)NMC * CH];
__device__ float g_aggm[(size_t)NMC * CH];
__device__ float g_ym[(size_t)NMC * CH];     // y_m = x_m @ Wl_mt^T
__device__ int   g_cnt_t[NTC];
__device__ int   g_cnt_m[NMC];
__device__ float g_inv_t[NTC];
__device__ float g_inv_m[NMC];

// ---------------- packed f32x2 FMA (FFMA2 — only reachable via PTX) ------------
union F2U { float2 f; unsigned long long u; };
__device__ __forceinline__ float2 ffma2(float2 a, float2 b, float2 c) {
    F2U A, B, Cc, D;
    A.f = a; B.f = b; Cc.f = c;
    asm("fma.rn.f32x2 %0, %1, %2, %3;" : "=l"(D.u) : "l"(A.u), "l"(B.u), "l"(Cc.u));
    return D.f;
}

// ---------------- degree / recip ----------------
__global__ void degree_kernel(const int* __restrict__ esrc, const int* __restrict__ edst, int E) {
    int t = blockIdx.x * blockDim.x + threadIdx.x;
    if (t < E) {
        atomicAdd(&g_cnt_t[esrc[t]], 1);
        atomicAdd(&g_cnt_m[edst[t]], 1);
    }
}

__global__ void recip_kernel(const int* __restrict__ cnt, float* __restrict__ inv, int n) {
    int t = blockIdx.x * blockDim.x + threadIdx.x;
    if (t < n) inv[t] = 1.0f / fmaxf((float)cnt[t], 1.0f);
}

// ---------------- mentor encoder: x_m0 = emb_m[mentor_id] ----------------
__global__ void gather_rows_kernel(const float* __restrict__ src, const int* __restrict__ ids,
                                   float* __restrict__ out, int n) {
    int t = blockIdx.x * blockDim.x + threadIdx.x;
    int e = t >> 4;
    if (e >= n) return;
    int c4 = (t & 15) << 2;
    int id = __ldg(&ids[e]);
    float4 v = *reinterpret_cast<const float4*>(&src[(size_t)id * CH + c4]);
    *reinterpret_cast<float4*>(&out[(size_t)e * CH + c4]) = v;
}

// ---------------- edge scatter-add: agg[sidx[e]] += feat[gidx[e]] --------------
__global__ void scatter_kernel(const float* __restrict__ feat, const int* __restrict__ gidx,
                               const int* __restrict__ sidx, float* __restrict__ agg, int E) {
    int t = blockIdx.x * blockDim.x + threadIdx.x;
    int e = t >> 4;
    if (e >= E) return;
    int c4 = (t & 15) << 2;
    int s = __ldg(&gidx[e]);
    int d = __ldg(&sidx[e]);
    float4 v = *reinterpret_cast<const float4*>(&feat[(size_t)s * CH + c4]);
    float* p = &agg[(size_t)d * CH + c4];
    asm volatile("red.global.add.v4.f32 [%0], {%1, %2, %3, %4};"
                 :: "l"(p), "f"(v.x), "f"(v.y), "f"(v.z), "f"(v.w) : "memory");
}

// ---------------- encoder GEMM: out = X[M,384] @ W[64,384]^T + b + emb[id] ----
// BM=128, BN=64, BK=32, 256 threads, 8x4 micro-tile per thread via f32x2 pairs.
__global__ __launch_bounds__(256)
void encoder_kernel(const float* __restrict__ X, const float* __restrict__ W,
                    const float* __restrict__ bias, const float* __restrict__ emb,
                    const int* __restrict__ ids, float* __restrict__ out, int M) {
    __shared__ float As[32][132];
    __shared__ float Ws[32][68];
    int tid = threadIdx.x;
    int tx = tid & 15, ty = tid >> 4;
    int row0 = blockIdx.x * 128;

    float2 acc[4][4];
#pragma unroll
    for (int i = 0; i < 4; i++)
#pragma unroll
        for (int j = 0; j < 4; j++) acc[i][j] = make_float2(0.f, 0.f);

    for (int kt = 0; kt < FT; kt += 32) {
#pragma unroll
        for (int i = 0; i < 4; i++) {
            int idx = tid + 256 * i;
            int r = idx >> 3;
            int kq = (idx & 7) << 2;
            int grow = row0 + r;
            float4 v = make_float4(0.f, 0.f, 0.f, 0.f);
            if (grow < M)
                v = *reinterpret_cast<const float4*>(&X[(size_t)grow * FT + kt + kq]);
            As[kq + 0][r] = v.x; As[kq + 1][r] = v.y;
            As[kq + 2][r] = v.z; As[kq + 3][r] = v.w;
        }
#pragma unroll
        for (int i = 0; i < 2; i++) {
            int idx = tid + 256 * i;
            int c = idx >> 3;
            int kq = (idx & 7) << 2;
            float4 v = *reinterpret_cast<const float4*>(&W[(size_t)c * FT + kt + kq]);
            Ws[kq + 0][c] = v.x; Ws[kq + 1][c] = v.y;
            Ws[kq + 2][c] = v.z; Ws[kq + 3][c] = v.w;
        }
        __syncthreads();
#pragma unroll
        for (int k = 0; k < 32; k++) {
            float4 a0 = *reinterpret_cast<const float4*>(&As[k][ty * 8]);
            float4 a1 = *reinterpret_cast<const float4*>(&As[k][ty * 8 + 4]);
            float4 w  = *reinterpret_cast<const float4*>(&Ws[k][tx * 4]);
            float2 ap[4] = { {a0.x, a0.y}, {a0.z, a0.w}, {a1.x, a1.y}, {a1.z, a1.w} };
            float2 wd[4] = { {w.x, w.x}, {w.y, w.y}, {w.z, w.z}, {w.w, w.w} };
#pragma unroll
            for (int rp = 0; rp < 4; rp++)
#pragma unroll
                for (int j = 0; j < 4; j++)
                    acc[rp][j] = ffma2(ap[rp], wd[j], acc[rp][j]);
        }
        __syncthreads();
    }

    float4 bv = *reinterpret_cast<const float4*>(&bias[tx * 4]);
#pragma unroll
    for (int rp = 0; rp < 4; rp++) {
#pragma unroll
        for (int s = 0; s < 2; s++) {
            int r = row0 + ty * 8 + rp * 2 + s;
            if (r < M) {
                int nid = __ldg(&ids[r]);
                float4 ev = *reinterpret_cast<const float4*>(&emb[(size_t)nid * CH + tx * 4]);
                float4 o;
                o.x = (s ? acc[rp][0].y : acc[rp][0].x) + bv.x + ev.x;
                o.y = (s ? acc[rp][1].y : acc[rp][1].x) + bv.y + ev.y;
                o.z = (s ? acc[rp][2].y : acc[rp][2].x) + bv.z + ev.z;
                o.w = (s ? acc[rp][3].y : acc[rp][3].x) + bv.w + ev.w;
                *reinterpret_cast<float4*>(&out[(size_t)r * CH + tx * 4]) = o;
            }
        }
    }
}

// ---------------- mentor SAGE layer GEMM (K=128: agg/inv + self) ---------------
template <bool RELU>
__global__ __launch_bounds__(256)
void sage_kernel(const float* __restrict__ Agg, const float* __restrict__ inv,
                 const float* __restrict__ Xs,
                 const float* __restrict__ Wl, const float* __restrict__ Wr,
                 const float* __restrict__ bias, float* __restrict__ out, int M) {
    __shared__ float As[32][132];
    __shared__ float Ws[32][68];
    int tid = threadIdx.x;
    int tx = tid & 15, ty = tid >> 4;
    int row0 = blockIdx.x * 128;

    float2 acc[4][4];
#pragma unroll
    for (int i = 0; i < 4; i++)
#pragma unroll
        for (int j = 0; j < 4; j++) acc[i][j] = make_float2(0.f, 0.f);

    for (int tt = 0; tt < 4; tt++) {
        const float* A  = (tt < 2) ? Agg : Xs;
        const float* Wp = (tt < 2) ? Wl  : Wr;
        bool do_scale = (tt < 2);
        int kt = (tt & 1) * 32;
#pragma unroll
        for (int i = 0; i < 4; i++) {
            int idx = tid + 256 * i;
            int r = idx >> 3;
            int kq = (idx & 7) << 2;
            int grow = row0 + r;
            float4 v = make_float4(0.f, 0.f, 0.f, 0.f);
            if (grow < M) {
                v = *reinterpret_cast<const float4*>(&A[(size_t)grow * CH + kt + kq]);
                if (do_scale) {
                    float sc = __ldg(&inv[grow]);
                    v.x *= sc; v.y *= sc; v.z *= sc; v.w *= sc;
                }
            }
            As[kq + 0][r] = v.x; As[kq + 1][r] = v.y;
            As[kq + 2][r] = v.z; As[kq + 3][r] = v.w;
        }
#pragma unroll
        for (int i = 0; i < 2; i++) {
            int idx = tid + 256 * i;
            int c = idx >> 3;
            int kq = (idx & 7) << 2;
            float4 v = *reinterpret_cast<const float4*>(&Wp[(size_t)c * CH + kt + kq]);
            Ws[kq + 0][c] = v.x; Ws[kq + 1][c] = v.y;
            Ws[kq + 2][c] = v.z; Ws[kq + 3][c] = v.w;
        }
        __syncthreads();
#pragma unroll
        for (int k = 0; k < 32; k++) {
            float4 a0 = *reinterpret_cast<const float4*>(&As[k][ty * 8]);
            float4 a1 = *reinterpret_cast<const float4*>(&As[k][ty * 8 + 4]);
            float4 w  = *reinterpret_cast<const float4*>(&Ws[k][tx * 4]);
            float2 ap[4] = { {a0.x, a0.y}, {a0.z, a0.w}, {a1.x, a1.y}, {a1.z, a1.w} };
            float2 wd[4] = { {w.x, w.x}, {w.y, w.y}, {w.z, w.z}, {w.w, w.w} };
#pragma unroll
            for (int rp = 0; rp < 4; rp++)
#pragma unroll
                for (int j = 0; j < 4; j++)
                    acc[rp][j] = ffma2(ap[rp], wd[j], acc[rp][j]);
        }
        __syncthreads();
    }

    float4 bv = *reinterpret_cast<const float4*>(&bias[tx * 4]);
#pragma unroll
    for (int rp = 0; rp < 4; rp++) {
#pragma unroll
        for (int s = 0; s < 2; s++) {
            int r = row0 + ty * 8 + rp * 2 + s;
            if (r < M) {
                float4 o;
                o.x = (s ? acc[rp][0].y : acc[rp][0].x) + bv.x;
                o.y = (s ? acc[rp][1].y : acc[rp][1].x) + bv.y;
                o.z = (s ? acc[rp][2].y : acc[rp][2].x) + bv.z;
                o.w = (s ? acc[rp][3].y : acc[rp][3].x) + bv.w;
                if (RELU) {
                    o.x = fmaxf(o.x, 0.f); o.y = fmaxf(o.y, 0.f);
                    o.z = fmaxf(o.z, 0.f); o.w = fmaxf(o.w, 0.f);
                }
                *reinterpret_cast<float4*>(&out[(size_t)r * CH + tx * 4]) = o;
            }
        }
    }
}

// ---------------- K=64 GEMM: out = act( X@W^T [+ bias] [+ aggY*inv] ) ----------
// Used for (a) mentor pre-transform y_m = x_m @ Wl_mt^T  (no bias/agg/relu)
//          (b) thesis SAGE:  out_t = act(x_t @ Wr^T + aggY*inv + b)
template <bool RELU, bool BIAS, bool ADDAGG>
__global__ __launch_bounds__(256)
void gemm64_kernel(const float* __restrict__ X, const float* __restrict__ W,
                   const float* __restrict__ bias,
                   const float* __restrict__ aggY, const float* __restrict__ inv,
                   float* __restrict__ out, int M) {
    __shared__ float As[32][132];
    __shared__ float Ws[32][68];
    int tid = threadIdx.x;
    int tx = tid & 15, ty = tid >> 4;
    int row0 = blockIdx.x * 128;

    float2 acc[4][4];
#pragma unroll
    for (int i = 0; i < 4; i++)
#pragma unroll
        for (int j = 0; j < 4; j++) acc[i][j] = make_float2(0.f, 0.f);

    for (int kt = 0; kt < CH; kt += 32) {
#pragma unroll
        for (int i = 0; i < 4; i++) {
            int idx = tid + 256 * i;
            int r = idx >> 3;
            int kq = (idx & 7) << 2;
            int grow = row0 + r;
            float4 v = make_float4(0.f, 0.f, 0.f, 0.f);
            if (grow < M)
                v = *reinterpret_cast<const float4*>(&X[(size_t)grow * CH + kt + kq]);
            As[kq + 0][r] = v.x; As[kq + 1][r] = v.y;
            As[kq + 2][r] = v.z; As[kq + 3][r] = v.w;
        }
#pragma unroll
        for (int i = 0; i < 2; i++) {
            int idx = tid + 256 * i;
            int c = idx >> 3;
            int kq = (idx & 7) << 2;
            float4 v = *reinterpret_cast<const float4*>(&W[(size_t)c * CH + kt + kq]);
            Ws[kq + 0][c] = v.x; Ws[kq + 1][c] = v.y;
            Ws[kq + 2][c] = v.z; Ws[kq + 3][c] = v.w;
        }
        __syncthreads();
#pragma unroll
        for (int k = 0; k < 32; k++) {
            float4 a0 = *reinterpret_cast<const float4*>(&As[k][ty * 8]);
            float4 a1 = *reinterpret_cast<const float4*>(&As[k][ty * 8 + 4]);
            float4 w  = *reinterpret_cast<const float4*>(&Ws[k][tx * 4]);
            float2 ap[4] = { {a0.x, a0.y}, {a0.z, a0.w}, {a1.x, a1.y}, {a1.z, a1.w} };
            float2 wd[4] = { {w.x, w.x}, {w.y, w.y}, {w.z, w.z}, {w.w, w.w} };
#pragma unroll
            for (int rp = 0; rp < 4; rp++)
#pragma unroll
                for (int j = 0; j < 4; j++)
                    acc[rp][j] = ffma2(ap[rp], wd[j], acc[rp][j]);
        }
        __syncthreads();
    }

    float4 bv = make_float4(0.f, 0.f, 0.f, 0.f);
    if (BIAS) bv = *reinterpret_cast<const float4*>(&bias[tx * 4]);
#pragma unroll
    for (int rp = 0; rp < 4; rp++) {
#pragma unroll
        for (int s = 0; s < 2; s++) {
            int r = row0 + ty * 8 + rp * 2 + s;
            if (r < M) {
                float4 o;
                o.x = (s ? acc[rp][0].y : acc[rp][0].x) + bv.x;
                o.y = (s ? acc[rp][1].y : acc[rp][1].x) + bv.y;
                o.z = (s ? acc[rp][2].y : acc[rp][2].x) + bv.z;
                o.w = (s ? acc[rp][3].y : acc[rp][3].x) + bv.w;
                if (ADDAGG) {
                    float sc = __ldg(&inv[r]);
                    float4 av = *reinterpret_cast<const float4*>(&aggY[(size_t)r * CH + tx * 4]);
                    o.x = fmaf(av.x, sc, o.x);
                    o.y = fmaf(av.y, sc, o.y);
                    o.z = fmaf(av.z, sc, o.z);
                    o.w = fmaf(av.w, sc, o.w);
                }
                if (RELU) {
                    o.x = fmaxf(o.x, 0.f); o.y = fmaxf(o.y, 0.f);
                    o.z = fmaxf(o.z, 0.f); o.w = fmaxf(o.w, 0.f);
                }
                *reinterpret_cast<float4*>(&out[(size_t)r * CH + tx * 4]) = o;
            }
        }
    }
}

// ---------------- edge dot-product classifier --------------------------------
__global__ void edge_dot_kernel(const float* __restrict__ xt, const float* __restrict__ xm,
                                const int* __restrict__ es, const int* __restrict__ ed,
                                float* __restrict__ out, int E) {
    int t = blockIdx.x * blockDim.x + threadIdx.x;
    int e = t >> 4;
    if (e >= E) return;
    int c4 = (t & 15) << 2;
    int s = __ldg(&es[e]);
    int d = __ldg(&ed[e]);
    float4 a = *reinterpret_cast<const float4*>(&xt[(size_t)s * CH + c4]);
    float4 b = *reinterpret_cast<const float4*>(&xm[(size_t)d * CH + c4]);
    float p = a.x * b.x + a.y * b.y + a.z * b.z + a.w * b.w;
    p += __shfl_down_sync(0xffffffffu, p, 8);
    p += __shfl_down_sync(0xffffffffu, p, 4);
    p += __shfl_down_sync(0xffffffffu, p, 2);
    p += __shfl_down_sync(0xffffffffu, p, 1);
    if ((t & 15) == 0) out[e] = p;
}

// ---------------- launch -----------------------------------------------------
extern "C" void kernel_launch(void* const* d_in, const int* in_sizes, int n_in,
                              void* d_out, int out_size) {
    const float* x_thesis  = (const float*)d_in[0];
    const int*   thesis_id = (const int*)d_in[1];
    const int*   mentor_id = (const int*)d_in[2];
    const int*   edge_src  = (const int*)d_in[3];
    const int*   edge_dst  = (const int*)d_in[4];
    const int*   el_src    = (const int*)d_in[5];
    const int*   el_dst    = (const int*)d_in[6];
    const float* lin_W     = (const float*)d_in[7];
    const float* lin_b     = (const float*)d_in[8];
    const float* emb_t     = (const float*)d_in[9];
    const float* emb_m     = (const float*)d_in[10];
    const float* Wl_tm0    = (const float*)d_in[11];
    const float* Wr_tm0    = (const float*)d_in[12];
    const float* b_tm0     = (const float*)d_in[13];
    const float* Wl_mt0    = (const float*)d_in[14];
    const float* Wr_mt0    = (const float*)d_in[15];
    const float* b_mt0     = (const float*)d_in[16];
    const float* Wl_tm1    = (const float*)d_in[17];
    const float* Wr_tm1    = (const float*)d_in[18];
    const float* b_tm1     = (const float*)d_in[19];
    const float* Wl_mt1    = (const float*)d_in[20];
    const float* Wr_mt1    = (const float*)d_in[21];
    const float* b_mt1     = (const float*)d_in[22];
    float* out = (float*)d_out;

    int nt = in_sizes[1];
    int nm = in_sizes[2];
    int E  = in_sizes[3];
    int EL = in_sizes[5];

    void *p_xt0, *p_xt1, *p_xt2, *p_aggt, *p_xm0, *p_xm1, *p_xm2, *p_aggm, *p_ym;
    void *p_cntt, *p_cntm, *p_invt, *p_invm;
    cudaGetSymbolAddress(&p_xt0, g_xt0);   cudaGetSymbolAddress(&p_xt1, g_xt1);
    cudaGetSymbolAddress(&p_xt2, g_xt2);   cudaGetSymbolAddress(&p_aggt, g_aggt);
    cudaGetSymbolAddress(&p_xm0, g_xm0);   cudaGetSymbolAddress(&p_xm1, g_xm1);
    cudaGetSymbolAddress(&p_xm2, g_xm2);   cudaGetSymbolAddress(&p_aggm, g_aggm);
    cudaGetSymbolAddress(&p_ym, g_ym);
    cudaGetSymbolAddress(&p_cntt, g_cnt_t); cudaGetSymbolAddress(&p_cntm, g_cnt_m);
    cudaGetSymbolAddress(&p_invt, g_inv_t); cudaGetSymbolAddress(&p_invm, g_inv_m);

    float* xt0 = (float*)p_xt0; float* xt1 = (float*)p_xt1; float* xt2 = (float*)p_xt2;
    float* aggt = (float*)p_aggt;
    float* xm0 = (float*)p_xm0; float* xm1 = (float*)p_xm1; float* xm2 = (float*)p_xm2;
    float* aggm = (float*)p_aggm; float* ym = (float*)p_ym;
    int* cntt = (int*)p_cntt; int* cntm = (int*)p_cntm;
    float* invt = (float*)p_invt; float* invm = (float*)p_invm;

    const int TB = 256;
    int gridE16  = (E * 16 + TB - 1) / TB;
    int gridEL16 = (EL * 16 + TB - 1) / TB;
    int gridNT   = (nt + 127) / 128;
    int gridNM   = (nm + 127) / 128;

    // ---- phase A: exactly 5 launches before the encoder so ncu (-s 5 -c 1)
    //      captures encoder_kernel next round ----
    cudaMemsetAsync(cntt, 0, (size_t)nt * sizeof(int));
    cudaMemsetAsync(cntm, 0, (size_t)nm * sizeof(int));
    degree_kernel<<<(E + TB - 1) / TB, TB>>>(edge_src, edge_dst, E);
    recip_kernel<<<(nt + TB - 1) / TB, TB>>>(cntt, invt, nt);
    recip_kernel<<<(nm + TB - 1) / TB, TB>>>(cntm, invm, nm);

    encoder_kernel<<<gridNT, TB>>>(x_thesis, lin_W, lin_b, emb_t, thesis_id, xt0, nt);
    gather_rows_kernel<<<(nm * 16 + TB - 1) / TB, TB>>>(emb_m, mentor_id, xm0, nm);

    // ---- layer 0 ----
    // pre-transform mentor rows for thesis aggregation: y_m = x_m @ Wl_mt0^T
    gemm64_kernel<false, false, false><<<gridNM, TB>>>(xm0, Wl_mt0, nullptr, nullptr, nullptr, ym, nm);
    cudaMemsetAsync(aggm, 0, (size_t)nm * CH * sizeof(float));
    cudaMemsetAsync(aggt, 0, (size_t)nt * CH * sizeof(float));
    scatter_kernel<<<gridE16, TB>>>(xt0, edge_src, edge_dst, aggm, E);
    scatter_kernel<<<gridE16, TB>>>(ym, edge_dst, edge_src, aggt, E);
    sage_kernel<true><<<gridNM, TB>>>(aggm, invm, xm0, Wl_tm0, Wr_tm0, b_tm0, xm1, nm);
    gemm64_kernel<true, true, true><<<gridNT, TB>>>(xt0, Wr_mt0, b_mt0, aggt, invt, xt1, nt);

    // ---- layer 1 ----
    gemm64_kernel<false, false, false><<<gridNM, TB>>>(xm1, Wl_mt1, nullptr, nullptr, nullptr, ym, nm);
    cudaMemsetAsync(aggm, 0, (size_t)nm * CH * sizeof(float));
    cudaMemsetAsync(aggt, 0, (size_t)nt * CH * sizeof(float));
    scatter_kernel<<<gridE16, TB>>>(xt1, edge_src, edge_dst, aggm, E);
    scatter_kernel<<<gridE16, TB>>>(ym, edge_dst, edge_src, aggt, E);
    sage_kernel<false><<<gridNM, TB>>>(aggm, invm, xm1, Wl_tm1, Wr_tm1, b_tm1, xm2, nm);
    gemm64_kernel<false, true, true><<<gridNT, TB>>>(xt1, Wr_mt1, b_mt1, aggt, invt, xt2, nt);

    // classifier
    edge_dot_kernel<<<gridEL16, TB>>>(xt2, xm2, el_src, el_dst, out, EL);
}